// round 16
// baseline (speedup 1.0000x reference)
#include <cuda_runtime.h>
#include <cuda_fp16.h>
#include <cstdint>
#include <cstddef>
#include <math.h>

#define Bn 4
#define Sn 2048
#define Dn 1024
#define Hn 16
#define DKn 64

// ---------------------------------------------------------------------------
// Scratch (alloc-free rule: __device__ globals)
// ---------------------------------------------------------------------------
__device__ __half g_qh[(size_t)Bn * Hn * Sn * DKn];       // Q fp16, pre-scaled log2e/8
__device__ __half g_kh[(size_t)Bn * Hn * Sn * DKn];       // K fp16
__device__ __half g_vh[(size_t)Bn * Hn * Sn * DKn];       // V fp16
__device__ __half g_ah[(size_t)Bn * Sn * Dn];             // attn out fp16 [b][s][h*64+d]
__device__ __half g_xh[(size_t)Bn * Sn * Dn];             // fp16(x)
__device__ __half g_wh[(size_t)3 * Hn * DKn * Dn];        // fp16(w_qkv)
__device__ __half g_woh[(size_t)Dn * Dn];                 // fp16(w_o)

// ---------------------------------------------------------------------------
// PTX helpers (sm_100 baseline)
// ---------------------------------------------------------------------------
__device__ __forceinline__ uint32_t smem_u32(const void* p) {
    uint32_t a;
    asm("{ .reg .u64 t; cvta.to.shared.u64 t, %1; cvt.u32.u64 %0, t; }"
        : "=r"(a) : "l"(p));
    return a;
}

__device__ __forceinline__ void cp16(uint32_t dst, const void* src) {
    asm volatile("cp.async.cg.shared.global [%0], [%1], 16;"
                 :: "r"(dst), "l"(src));
}
#define CP_COMMIT() asm volatile("cp.async.commit_group;" ::: "memory")
#define CP_WAIT(n)  asm volatile("cp.async.wait_group %0;" :: "n"(n) : "memory")

__device__ __forceinline__ uint32_t pack_f16(float hi, float lo) {
    uint32_t d;
    asm("cvt.rn.f16x2.f32 %0, %1, %2;" : "=r"(d) : "f"(hi), "f"(lo));
    return d;
}

__device__ __forceinline__ void ldsm4(uint32_t* r, uint32_t addr) {
    asm volatile("ldmatrix.sync.aligned.m8n8.x4.shared.b16 {%0,%1,%2,%3}, [%4];"
                 : "=r"(r[0]), "=r"(r[1]), "=r"(r[2]), "=r"(r[3]) : "r"(addr));
}
__device__ __forceinline__ void ldsm4t(uint32_t* r, uint32_t addr) {
    asm volatile("ldmatrix.sync.aligned.m8n8.x4.trans.shared.b16 {%0,%1,%2,%3}, [%4];"
                 : "=r"(r[0]), "=r"(r[1]), "=r"(r[2]), "=r"(r[3]) : "r"(addr));
}

// fp32-accumulator fp16 mma (rt~16)
__device__ __forceinline__ void mma_f16(float* d, const uint32_t* a, const uint32_t* b) {
    asm volatile("mma.sync.aligned.m16n8k16.row.col.f32.f16.f16.f32 "
                 "{%0,%1,%2,%3}, {%4,%5,%6,%7}, {%8,%9}, {%0,%1,%2,%3};"
                 : "+f"(d[0]), "+f"(d[1]), "+f"(d[2]), "+f"(d[3])
                 : "r"(a[0]), "r"(a[1]), "r"(a[2]), "r"(a[3]), "r"(b[0]), "r"(b[1]));
}

// fp16-accumulator fp16 mma (rt~8, 2x rate) — D/C are 2 b32 (f16x2) regs.
// Lane layout matches the f32 variant: d0 = {c0,c1} (row lr), d1 = {c2,c3} (row lr+8).
__device__ __forceinline__ void mma_f16h(uint32_t* d, const uint32_t* a, const uint32_t* b) {
    asm volatile("mma.sync.aligned.m16n8k16.row.col.f16.f16.f16.f16 "
                 "{%0,%1}, {%2,%3,%4,%5}, {%6,%7}, {%0,%1};"
                 : "+r"(d[0]), "+r"(d[1])
                 : "r"(a[0]), "r"(a[1]), "r"(a[2]), "r"(a[3]), "r"(b[0]), "r"(b[1]));
}

// ---------------------------------------------------------------------------
// fp32 -> fp16 pre-pass, all three inputs in ONE launch (range dispatch)
// ---------------------------------------------------------------------------
__global__ void __launch_bounds__(256) cvt_all(
    const float4* __restrict__ x, const float4* __restrict__ w,
    const float4* __restrict__ wo,
    uint2* __restrict__ xo, uint2* __restrict__ wqo, uint2* __restrict__ woo,
    int nx, int nw, int nwo)
{
    int i = blockIdx.x * 256 + threadIdx.x;
    const float4* src; uint2* dst; int off;
    if (i < nx)                { src = x;  dst = xo;  off = i; }
    else if (i < nx + nw)      { src = w;  dst = wqo; off = i - nx; }
    else if (i < nx + nw + nwo){ src = wo; dst = woo; off = i - nx - nw; }
    else return;
    float4 v = src[off];
    uint2 o;
    o.x = pack_f16(v.y, v.x);
    o.y = pack_f16(v.w, v.z);
    dst[off] = o;
}

// ---------------------------------------------------------------------------
// fp16 GEMM: C[M,N] = A[M,K] * B[N,K]^T, fp32 accumulate.   (unchanged R14)
// 128x128 CTA tile, BK=64, 8 warps (2x4), warp tile 64x32, 3-stage cp.async,
// single barrier per K-chunk. fp16 rows stride 72.
// REMAP==0: emit Q(x log2e/8)/K/V fp16 into g_qh/g_kh/g_vh; REMAP==1: fp32 C.
// ---------------------------------------------------------------------------
#define HLDS 72
#define HMAT (128 * HLDS * 2)          // 18432 B per matrix tile
#define HSTG (2 * HMAT)                // 36864 B per stage
#define G_SMEM (3 * HSTG)              // 110592

#define QSCALE 0.1803368801111204f     // (1/8) * log2(e)

template <int REMAP>
__global__ void __launch_bounds__(256, 2) gemm_f16(
    const __half* __restrict__ A, const __half* __restrict__ Bm,
    float* __restrict__ C, int M, int N, int K)
{
    extern __shared__ __half sg[];
    const uint32_t sb = smem_u32(sg);
    const int tid = threadIdx.x, lane = tid & 31, wid = tid >> 5;
    const int wm = wid >> 2, wn = wid & 3;              // 2 x 4 warp grid
    const int lr = lane >> 2, lc = lane & 3;
    const int bm = blockIdx.y * 128, bn = blockIdx.x * 128;
    const int NC = K >> 6;                              // BK = 64

    const __half* gA = A + (size_t)bm * K;
    const __half* gB = Bm + (size_t)bn * K;

    auto fill = [&](int s, int c) {
        const uint32_t base = sb + s * HSTG;
        const int kof = c * 64;
#pragma unroll
        for (int u = 0; u < 4; u++) {
            const int ch = tid + u * 256;               // 0..1023
            const int row = ch >> 3, c8 = (ch & 7) << 3;  // f16 units
            cp16(base + (uint32_t)(row * HLDS + c8) * 2,
                 gA + (size_t)row * K + kof + c8);
            cp16(base + HMAT + (uint32_t)(row * HLDS + c8) * 2,
                 gB + (size_t)row * K + kof + c8);
        }
        CP_COMMIT();
    };

    fill(0, 0);
    if (NC > 1) fill(1, 1);

    float acc[4][4][4];
#pragma unroll
    for (int i = 0; i < 4; i++)
#pragma unroll
        for (int j = 0; j < 4; j++)
#pragma unroll
            for (int e = 0; e < 4; e++) acc[i][j][e] = 0.f;

    // ldmatrix lane addressing (byte offsets)
    const uint32_t aOff = (uint32_t)((wm * 64 + (lane & 15)) * HLDS + (lane >> 4) * 8) * 2;
    const uint32_t bOff = (uint32_t)((wn * 32 + (lane >> 4) * 8 + (lane & 7)) * HLDS
                                     + ((lane >> 3) & 1) * 8) * 2;

    for (int c = 0; c < NC; c++) {
        const int s = c % 3;
        if (c < NC - 1) { CP_WAIT(1); } else { CP_WAIT(0); }
        __syncthreads();
        // Barrier certifies all warps finished reading stage (c+2)%3 at c-1.
        if (c + 2 < NC) fill((c + 2) % 3, c + 2);

        const uint32_t aB = sb + s * HSTG + aOff;
        const uint32_t bB = sb + s * HSTG + (uint32_t)HMAT + bOff;

#pragma unroll
        for (int t = 0; t < 4; t++) {                   // k = 16t
            uint32_t a[4][4], bq[2][4];
#pragma unroll
            for (int i = 0; i < 4; i++)
                ldsm4(a[i], aB + (uint32_t)(i * 16 * HLDS + t * 16) * 2);
#pragma unroll
            for (int jp = 0; jp < 2; jp++)
                ldsm4(bq[jp], bB + (uint32_t)(jp * 16 * HLDS + t * 16) * 2);
#pragma unroll
            for (int jp = 0; jp < 2; jp++)
#pragma unroll
                for (int i = 0; i < 4; i++) {
                    mma_f16(acc[i][2 * jp],     a[i], &bq[jp][0]);
                    mma_f16(acc[i][2 * jp + 1], a[i], &bq[jp][2]);
                }
        }
    }

    const int fc = lc << 1;
#pragma unroll
    for (int i = 0; i < 4; i++) {
#pragma unroll
        for (int j = 0; j < 4; j++) {
            const int n = bn + wn * 32 + j * 8 + fc;
#pragma unroll
            for (int half = 0; half < 2; half++) {
                const int m = bm + wm * 64 + i * 16 + lr + half * 8;
                float2 v = make_float2(acc[i][j][half * 2], acc[i][j][half * 2 + 1]);
                if (REMAP == 0) {
                    const int q = n >> 10, h = (n >> 6) & 15, kd = n & 63;
                    const int b = m >> 11, s2 = m & 2047;
                    const float sc = (q == 0) ? QSCALE : 1.0f;   // Q scale (log2 domain)
                    __half* dst = (q == 0) ? g_qh : ((q == 1) ? g_kh : g_vh);
                    *(uint32_t*)&dst[((((size_t)b * Hn + h) * Sn + s2) * DKn + kd)] =
                        pack_f16(v.y * sc, v.x * sc);
                } else {
                    *(float2*)&C[(size_t)m * N + n] = v;
                }
            }
        }
    }
}

// ---------------------------------------------------------------------------
// Causal flash attention. S = QK^T in fp16-ACCUMULATOR mma (2x rate; softmax
// normalization suppresses the extra rounding), unpacked to fp32 for masking/
// softmax; PV keeps fp32 accumulators. Softmax in log2 domain.
// ---------------------------------------------------------------------------
#define FQL2 72                             // f16 stride (144B rows)
#define FKB2 (64 * FQL2 * 2)                // 9216 B per K (or V) tile
#define FSTG2 (2 * FKB2)                    // 18432
#define F_SMEM (128 * FQL2 * 2 + 2 * FSTG2) // 55296

__global__ void __launch_bounds__(256, 2) flash_f16()
{
    extern __shared__ __half smh[];
    const uint32_t sbQ  = smem_u32(smh);
    const uint32_t sbKV = sbQ + 128 * FQL2 * 2;

    const int qt = (Sn / 128 - 1) - blockIdx.x;   // largest workload first
    const int h = blockIdx.y, b = blockIdx.z;
    const int tid = threadIdx.x;
    const int lane = tid & 31, wid = tid >> 5;
    const int lr = lane >> 2, lc = lane & 3;

    const size_t headoff = (((size_t)b * Hn + h) * Sn) * DKn;
    const __half* Qg = g_qh + headoff;
    const __half* Kg = g_kh + headoff;
    const __half* Vg = g_vh + headoff;

    auto fillKV = [&](int s, int kt) {
        const uint32_t base = sbKV + s * FSTG2;
#pragma unroll
        for (int u = 0; u < 2; u++) {
            const int ch = tid + u * 256;             // 0..511
            const int r = ch >> 3, c8 = (ch & 7) << 3;
            cp16(base + (uint32_t)(r * FQL2 + c8) * 2,
                 Kg + (size_t)(kt * 64 + r) * DKn + c8);
            cp16(base + FKB2 + (uint32_t)(r * FQL2 + c8) * 2,
                 Vg + (size_t)(kt * 64 + r) * DKn + c8);
        }
        CP_COMMIT();
    };

    const int KT = 2 * qt + 2;
    fillKV(0, 0);

#pragma unroll
    for (int u = 0; u < 4; u++) {
        const int idx = tid + u * 256;
        const int r = idx >> 3, c8 = (idx & 7) << 3;
        *(uint4*)(smh + r * FQL2 + c8) =
            *(const uint4*)(Qg + (size_t)(qt * 128 + r) * DKn + c8);
    }

    float oacc[8][4];
#pragma unroll
    for (int j = 0; j < 8; j++)
#pragma unroll
        for (int e = 0; e < 4; e++) oacc[j][e] = 0.f;
    float m0 = -1e30f, m1 = -1e30f, l0 = 0.f, l1 = 0.f;

    const uint32_t qOff = sbQ +
        (uint32_t)((wid * 16 + (lane & 15)) * FQL2 + (lane >> 4) * 8) * 2;
    const uint32_t kOff =
        (uint32_t)(((lane >> 4) * 8 + (lane & 7)) * FQL2 + ((lane >> 3) & 1) * 8) * 2;
    const uint32_t vOff =
        (uint32_t)((((lane >> 3) & 1) * 8 + (lane & 7)) * FQL2 + (lane >> 4) * 8) * 2;

    for (int kt = 0; kt < KT; kt++) {
        const int s = kt & 1;
        CP_WAIT(0);
        __syncthreads();
        // Barrier certifies all warps finished reading stage s^1 at kt-1
        // (and makes the Q-tile stores visible on kt==0) -> refill s^1 now.
        if (kt + 1 < KT) fillKV(s ^ 1, kt + 1);

        const uint32_t ksb = sbKV + s * FSTG2;
        const uint32_t vtb = ksb + FKB2;

        // S = (log2e/8) Q K^T  — fp16 accumulators (2x mma rate)
        uint32_t sh[8][2];
#pragma unroll
        for (int j = 0; j < 8; j++) { sh[j][0] = 0u; sh[j][1] = 0u; }

#pragma unroll
        for (int t = 0; t < 4; t++) {
            uint32_t a[4];
            ldsm4(a, qOff + (uint32_t)(t * 16) * 2);
#pragma unroll
            for (int jp = 0; jp < 4; jp++) {
                uint32_t kq[4];
                ldsm4(kq, ksb + kOff + (uint32_t)(jp * 16 * FQL2 + t * 16) * 2);
                mma_f16h(sh[2 * jp],     a, &kq[0]);
                mma_f16h(sh[2 * jp + 1], a, &kq[2]);
            }
        }

        // Unpack to fp32; downstream identical to R14.
        float sacc[8][4];
#pragma unroll
        for (int j = 0; j < 8; j++) {
            const __half2 h0 = *(__half2*)&sh[j][0];
            const __half2 h1 = *(__half2*)&sh[j][1];
            sacc[j][0] = __low2float(h0);  sacc[j][1] = __high2float(h0);
            sacc[j][2] = __low2float(h1);  sacc[j][3] = __high2float(h1);
        }

        if (kt * 64 + 63 > qt * 128) {
            const int qr0 = qt * 128 + wid * 16 + lr;
#pragma unroll
            for (int j = 0; j < 8; j++) {
                const int kc = kt * 64 + j * 8 + 2 * lc;
                if (kc     > qr0)     sacc[j][0] = -1e30f;
                if (kc + 1 > qr0)     sacc[j][1] = -1e30f;
                if (kc     > qr0 + 8) sacc[j][2] = -1e30f;
                if (kc + 1 > qr0 + 8) sacc[j][3] = -1e30f;
            }
        }

        float pm0 = -1e30f, pm1 = -1e30f;
#pragma unroll
        for (int j = 0; j < 8; j++) {
            pm0 = fmaxf(pm0, fmaxf(sacc[j][0], sacc[j][1]));
            pm1 = fmaxf(pm1, fmaxf(sacc[j][2], sacc[j][3]));
        }
        pm0 = fmaxf(pm0, __shfl_xor_sync(0xffffffffu, pm0, 1));
        pm0 = fmaxf(pm0, __shfl_xor_sync(0xffffffffu, pm0, 2));
        pm1 = fmaxf(pm1, __shfl_xor_sync(0xffffffffu, pm1, 1));
        pm1 = fmaxf(pm1, __shfl_xor_sync(0xffffffffu, pm1, 2));
        const float nm0 = fmaxf(m0, pm0), nm1 = fmaxf(m1, pm1);

        float sum0 = 0.f, sum1 = 0.f;
#pragma unroll
        for (int j = 0; j < 8; j++) {
            sacc[j][0] = exp2f(sacc[j][0] - nm0);
            sacc[j][1] = exp2f(sacc[j][1] - nm0);
            sacc[j][2] = exp2f(sacc[j][2] - nm1);
            sacc[j][3] = exp2f(sacc[j][3] - nm1);
            sum0 += sacc[j][0] + sacc[j][1];
            sum1 += sacc[j][2] + sacc[j][3];
        }
        sum0 += __shfl_xor_sync(0xffffffffu, sum0, 1);
        sum0 += __shfl_xor_sync(0xffffffffu, sum0, 2);
        sum1 += __shfl_xor_sync(0xffffffffu, sum1, 1);
        sum1 += __shfl_xor_sync(0xffffffffu, sum1, 2);

        const float al0 = exp2f(m0 - nm0), al1 = exp2f(m1 - nm1);
        l0 = l0 * al0 + sum0; l1 = l1 * al1 + sum1;
        m0 = nm0; m1 = nm1;
#pragma unroll
        for (int j = 0; j < 8; j++) {
            oacc[j][0] *= al0; oacc[j][1] *= al0;
            oacc[j][2] *= al1; oacc[j][3] *= al1;
        }

        // O += P V  (fp32 accumulators — error budget protected)
#pragma unroll
        for (int t = 0; t < 4; t++) {
            uint32_t ph[4];
            ph[0] = pack_f16(sacc[2 * t][1],     sacc[2 * t][0]);
            ph[1] = pack_f16(sacc[2 * t][3],     sacc[2 * t][2]);
            ph[2] = pack_f16(sacc[2 * t + 1][1], sacc[2 * t + 1][0]);
            ph[3] = pack_f16(sacc[2 * t + 1][3], sacc[2 * t + 1][2]);
#pragma unroll
            for (int jp = 0; jp < 4; jp++) {
                uint32_t vq[4];
                ldsm4t(vq, vtb + vOff + (uint32_t)(t * 16 * FQL2 + jp * 16) * 2);
                mma_f16(oacc[2 * jp],     ph, &vq[0]);
                mma_f16(oacc[2 * jp + 1], ph, &vq[2]);
            }
        }
    }

    // Epilogue: normalize, emit fp16 (feeds fp16 out-proj)
    const float inv0 = 1.f / l0, inv1 = 1.f / l1;
    const int r0 = qt * 128 + wid * 16 + lr;
#pragma unroll
    for (int j2 = 0; j2 < 8; j2++) {
        const int col = h * 64 + j2 * 8 + 2 * lc;
        *(uint32_t*)&g_ah[((size_t)b * Sn + r0) * Dn + col] =
            pack_f16(oacc[j2][1] * inv0, oacc[j2][0] * inv0);
        *(uint32_t*)&g_ah[((size_t)b * Sn + r0 + 8) * Dn + col] =
            pack_f16(oacc[j2][3] * inv1, oacc[j2][2] * inv1);
    }
}

// ---------------------------------------------------------------------------

extern "C" void kernel_launch(void* const* d_in, const int* in_sizes, int n_in,
                              void* d_out, int out_size)
{
    const float* x     = (const float*)d_in[0];  // [B,S,D]
    const float* w_qkv = (const float*)d_in[1];  // [3,H,DK,D]
    const float* w_o   = (const float*)d_in[2];  // [D,D]
    float* out = (float*)d_out;                  // [B,S,D]

    const int M = Bn * Sn;   // 8192

    (void)cudaFuncSetAttribute(flash_f16,
                               cudaFuncAttributeMaxDynamicSharedMemorySize, F_SMEM);
    (void)cudaFuncSetAttribute(gemm_f16<0>,
                               cudaFuncAttributeMaxDynamicSharedMemorySize, G_SMEM);
    (void)cudaFuncSetAttribute(gemm_f16<1>,
                               cudaFuncAttributeMaxDynamicSharedMemorySize, G_SMEM);

    __half *xh, *wh, *woh, *ah;
    (void)cudaGetSymbolAddress((void**)&xh, g_xh);
    (void)cudaGetSymbolAddress((void**)&wh, g_wh);
    (void)cudaGetSymbolAddress((void**)&woh, g_woh);
    (void)cudaGetSymbolAddress((void**)&ah, g_ah);

    // 0) fp32 -> fp16 pre-pass, single launch
    {
        const int nx  = M * Dn / 4;
        const int nw  = 3 * Hn * DKn * Dn / 4;
        const int nwo = Dn * Dn / 4;
        const int tot = nx + nw + nwo;
        cvt_all<<<(tot + 255) / 256, 256>>>(
            (const float4*)x, (const float4*)w_qkv, (const float4*)w_o,
            (uint2*)xh, (uint2*)wh, (uint2*)woh, nx, nw, nwo);
    }

    // 1) QKV projection (fp16 mma) -> g_qh/g_kh/g_vh
    {
        dim3 grid(3 * Hn * DKn / 128, M / 128);  // (24, 64)
        gemm_f16<0><<<grid, 256, G_SMEM>>>(xh, wh, nullptr, M, 3 * Hn * DKn, Dn);
    }

    // 2) Causal flash attention (fp16 mma, f16-acc S) -> g_ah
    {
        dim3 grid(Sn / 128, Hn, Bn);  // (16, 16, 4)
        flash_f16<<<grid, 256, F_SMEM>>>();
    }

    // 3) Output projection (fp16 mma) -> out
    {
        dim3 grid(Dn / 128, M / 128);  // (8, 64)
        gemm_f16<1><<<grid, 256, G_SMEM>>>(ah, woh, out, M, Dn, Dn);
    }
}

// round 17
// speedup vs baseline: 1.0153x; 1.0153x over previous
#include <cuda_runtime.h>
#include <cuda_fp16.h>
#include <cstdint>
#include <cstddef>
#include <math.h>

#define Bn 4
#define Sn 2048
#define Dn 1024
#define Hn 16
#define DKn 64

// ---------------------------------------------------------------------------
// Scratch (alloc-free rule: __device__ globals)
// ---------------------------------------------------------------------------
__device__ __half g_qh[(size_t)Bn * Hn * Sn * DKn];       // Q fp16, pre-scaled log2e/8
__device__ __half g_kh[(size_t)Bn * Hn * Sn * DKn];       // K fp16
__device__ __half g_vh[(size_t)Bn * Hn * Sn * DKn];       // V fp16
__device__ __half g_ah[(size_t)Bn * Sn * Dn];             // attn out fp16 [b][s][h*64+d]
__device__ __half g_xh[(size_t)Bn * Sn * Dn];             // fp16(x)
__device__ __half g_wh[(size_t)3 * Hn * DKn * Dn];        // fp16(w_qkv)
__device__ __half g_woh[(size_t)Dn * Dn];                 // fp16(w_o)

// ---------------------------------------------------------------------------
// PTX helpers (sm_100 baseline)
// ---------------------------------------------------------------------------
__device__ __forceinline__ uint32_t smem_u32(const void* p) {
    uint32_t a;
    asm("{ .reg .u64 t; cvta.to.shared.u64 t, %1; cvt.u32.u64 %0, t; }"
        : "=r"(a) : "l"(p));
    return a;
}

__device__ __forceinline__ void cp16(uint32_t dst, const void* src) {
    asm volatile("cp.async.cg.shared.global [%0], [%1], 16;"
                 :: "r"(dst), "l"(src));
}
#define CP_COMMIT() asm volatile("cp.async.commit_group;" ::: "memory")
#define CP_WAIT(n)  asm volatile("cp.async.wait_group %0;" :: "n"(n) : "memory")

__device__ __forceinline__ uint32_t pack_f16(float hi, float lo) {
    uint32_t d;
    asm("cvt.rn.f16x2.f32 %0, %1, %2;" : "=r"(d) : "f"(hi), "f"(lo));
    return d;
}

__device__ __forceinline__ uint32_t ex2_f16x2(uint32_t x) {
    uint32_t d;
    asm("ex2.approx.f16x2 %0, %1;" : "=r"(d) : "r"(x));
    return d;
}

__device__ __forceinline__ void ldsm4(uint32_t* r, uint32_t addr) {
    asm volatile("ldmatrix.sync.aligned.m8n8.x4.shared.b16 {%0,%1,%2,%3}, [%4];"
                 : "=r"(r[0]), "=r"(r[1]), "=r"(r[2]), "=r"(r[3]) : "r"(addr));
}
__device__ __forceinline__ void ldsm4t(uint32_t* r, uint32_t addr) {
    asm volatile("ldmatrix.sync.aligned.m8n8.x4.trans.shared.b16 {%0,%1,%2,%3}, [%4];"
                 : "=r"(r[0]), "=r"(r[1]), "=r"(r[2]), "=r"(r[3]) : "r"(addr));
}

// fp32-accumulator fp16 mma (rt~16)
__device__ __forceinline__ void mma_f16(float* d, const uint32_t* a, const uint32_t* b) {
    asm volatile("mma.sync.aligned.m16n8k16.row.col.f32.f16.f16.f32 "
                 "{%0,%1,%2,%3}, {%4,%5,%6,%7}, {%8,%9}, {%0,%1,%2,%3};"
                 : "+f"(d[0]), "+f"(d[1]), "+f"(d[2]), "+f"(d[3])
                 : "r"(a[0]), "r"(a[1]), "r"(a[2]), "r"(a[3]), "r"(b[0]), "r"(b[1]));
}

// ---------------------------------------------------------------------------
// fp32 -> fp16 pre-pass, all three inputs in ONE launch (range dispatch)
// ---------------------------------------------------------------------------
__global__ void __launch_bounds__(256) cvt_all(
    const float4* __restrict__ x, const float4* __restrict__ w,
    const float4* __restrict__ wo,
    uint2* __restrict__ xo, uint2* __restrict__ wqo, uint2* __restrict__ woo,
    int nx, int nw, int nwo)
{
    int i = blockIdx.x * 256 + threadIdx.x;
    const float4* src; uint2* dst; int off;
    if (i < nx)                { src = x;  dst = xo;  off = i; }
    else if (i < nx + nw)      { src = w;  dst = wqo; off = i - nx; }
    else if (i < nx + nw + nwo){ src = wo; dst = woo; off = i - nx - nw; }
    else return;
    float4 v = src[off];
    uint2 o;
    o.x = pack_f16(v.y, v.x);
    o.y = pack_f16(v.w, v.z);
    dst[off] = o;
}

// ---------------------------------------------------------------------------
// fp16 GEMM: C[M,N] = A[M,K] * B[N,K]^T, fp32 accumulate.   (unchanged R14)
// 128x128 CTA tile, BK=64, 8 warps (2x4), warp tile 64x32, 3-stage cp.async,
// single barrier per K-chunk. fp16 rows stride 72.
// REMAP==0: emit Q(x log2e/8)/K/V fp16 into g_qh/g_kh/g_vh; REMAP==1: fp32 C.
// ---------------------------------------------------------------------------
#define HLDS 72
#define HMAT (128 * HLDS * 2)          // 18432 B per matrix tile
#define HSTG (2 * HMAT)                // 36864 B per stage
#define G_SMEM (3 * HSTG)              // 110592

#define QSCALE 0.1803368801111204f     // (1/8) * log2(e)

template <int REMAP>
__global__ void __launch_bounds__(256, 2) gemm_f16(
    const __half* __restrict__ A, const __half* __restrict__ Bm,
    float* __restrict__ C, int M, int N, int K)
{
    extern __shared__ __half sg[];
    const uint32_t sb = smem_u32(sg);
    const int tid = threadIdx.x, lane = tid & 31, wid = tid >> 5;
    const int wm = wid >> 2, wn = wid & 3;              // 2 x 4 warp grid
    const int lr = lane >> 2, lc = lane & 3;
    const int bm = blockIdx.y * 128, bn = blockIdx.x * 128;
    const int NC = K >> 6;                              // BK = 64

    const __half* gA = A + (size_t)bm * K;
    const __half* gB = Bm + (size_t)bn * K;

    auto fill = [&](int s, int c) {
        const uint32_t base = sb + s * HSTG;
        const int kof = c * 64;
#pragma unroll
        for (int u = 0; u < 4; u++) {
            const int ch = tid + u * 256;               // 0..1023
            const int row = ch >> 3, c8 = (ch & 7) << 3;  // f16 units
            cp16(base + (uint32_t)(row * HLDS + c8) * 2,
                 gA + (size_t)row * K + kof + c8);
            cp16(base + HMAT + (uint32_t)(row * HLDS + c8) * 2,
                 gB + (size_t)row * K + kof + c8);
        }
        CP_COMMIT();
    };

    fill(0, 0);
    if (NC > 1) fill(1, 1);

    float acc[4][4][4];
#pragma unroll
    for (int i = 0; i < 4; i++)
#pragma unroll
        for (int j = 0; j < 4; j++)
#pragma unroll
            for (int e = 0; e < 4; e++) acc[i][j][e] = 0.f;

    // ldmatrix lane addressing (byte offsets)
    const uint32_t aOff = (uint32_t)((wm * 64 + (lane & 15)) * HLDS + (lane >> 4) * 8) * 2;
    const uint32_t bOff = (uint32_t)((wn * 32 + (lane >> 4) * 8 + (lane & 7)) * HLDS
                                     + ((lane >> 3) & 1) * 8) * 2;

    for (int c = 0; c < NC; c++) {
        const int s = c % 3;
        if (c < NC - 1) { CP_WAIT(1); } else { CP_WAIT(0); }
        __syncthreads();
        // Barrier certifies all warps finished reading stage (c+2)%3 at c-1.
        if (c + 2 < NC) fill((c + 2) % 3, c + 2);

        const uint32_t aB = sb + s * HSTG + aOff;
        const uint32_t bB = sb + s * HSTG + (uint32_t)HMAT + bOff;

#pragma unroll
        for (int t = 0; t < 4; t++) {                   // k = 16t
            uint32_t a[4][4], bq[2][4];
#pragma unroll
            for (int i = 0; i < 4; i++)
                ldsm4(a[i], aB + (uint32_t)(i * 16 * HLDS + t * 16) * 2);
#pragma unroll
            for (int jp = 0; jp < 2; jp++)
                ldsm4(bq[jp], bB + (uint32_t)(jp * 16 * HLDS + t * 16) * 2);
#pragma unroll
            for (int jp = 0; jp < 2; jp++)
#pragma unroll
                for (int i = 0; i < 4; i++) {
                    mma_f16(acc[i][2 * jp],     a[i], &bq[jp][0]);
                    mma_f16(acc[i][2 * jp + 1], a[i], &bq[jp][2]);
                }
        }
    }

    const int fc = lc << 1;
#pragma unroll
    for (int i = 0; i < 4; i++) {
#pragma unroll
        for (int j = 0; j < 4; j++) {
            const int n = bn + wn * 32 + j * 8 + fc;
#pragma unroll
            for (int half = 0; half < 2; half++) {
                const int m = bm + wm * 64 + i * 16 + lr + half * 8;
                float2 v = make_float2(acc[i][j][half * 2], acc[i][j][half * 2 + 1]);
                if (REMAP == 0) {
                    const int q = n >> 10, h = (n >> 6) & 15, kd = n & 63;
                    const int b = m >> 11, s2 = m & 2047;
                    const float sc = (q == 0) ? QSCALE : 1.0f;   // Q scale (log2 domain)
                    __half* dst = (q == 0) ? g_qh : ((q == 1) ? g_kh : g_vh);
                    *(uint32_t*)&dst[((((size_t)b * Hn + h) * Sn + s2) * DKn + kd)] =
                        pack_f16(v.y * sc, v.x * sc);
                } else {
                    *(float2*)&C[(size_t)m * N + n] = v;
                }
            }
        }
    }
}

// ---------------------------------------------------------------------------
// Causal flash attention, fp16 operands / fp32 accumulators (S and PV).
// Softmax in log2 domain; probabilities computed with ex2.approx.f16x2 on
// packed (s - m) pairs — the result IS the PV A-fragment operand, so the
// per-tile PV packs disappear and MUFU work halves. Row sums via f32 cvt
// of the same f16 probs (self-consistent normalization).
// ---------------------------------------------------------------------------
#define FQL2 72                             // f16 stride (144B rows)
#define FKB2 (64 * FQL2 * 2)                // 9216 B per K (or V) tile
#define FSTG2 (2 * FKB2)                    // 18432
#define F_SMEM (128 * FQL2 * 2 + 2 * FSTG2) // 55296

__global__ void __launch_bounds__(256, 2) flash_f16()
{
    extern __shared__ __half smh[];
    const uint32_t sbQ  = smem_u32(smh);
    const uint32_t sbKV = sbQ + 128 * FQL2 * 2;

    const int qt = (Sn / 128 - 1) - blockIdx.x;   // largest workload first
    const int h = blockIdx.y, b = blockIdx.z;
    const int tid = threadIdx.x;
    const int lane = tid & 31, wid = tid >> 5;
    const int lr = lane >> 2, lc = lane & 3;

    const size_t headoff = (((size_t)b * Hn + h) * Sn) * DKn;
    const __half* Qg = g_qh + headoff;
    const __half* Kg = g_kh + headoff;
    const __half* Vg = g_vh + headoff;

    auto fillKV = [&](int s, int kt) {
        const uint32_t base = sbKV + s * FSTG2;
#pragma unroll
        for (int u = 0; u < 2; u++) {
            const int ch = tid + u * 256;             // 0..511
            const int r = ch >> 3, c8 = (ch & 7) << 3;
            cp16(base + (uint32_t)(r * FQL2 + c8) * 2,
                 Kg + (size_t)(kt * 64 + r) * DKn + c8);
            cp16(base + FKB2 + (uint32_t)(r * FQL2 + c8) * 2,
                 Vg + (size_t)(kt * 64 + r) * DKn + c8);
        }
        CP_COMMIT();
    };

    const int KT = 2 * qt + 2;
    fillKV(0, 0);

#pragma unroll
    for (int u = 0; u < 4; u++) {
        const int idx = tid + u * 256;
        const int r = idx >> 3, c8 = (idx & 7) << 3;
        *(uint4*)(smh + r * FQL2 + c8) =
            *(const uint4*)(Qg + (size_t)(qt * 128 + r) * DKn + c8);
    }

    float oacc[8][4];
#pragma unroll
    for (int j = 0; j < 8; j++)
#pragma unroll
        for (int e = 0; e < 4; e++) oacc[j][e] = 0.f;
    float m0 = -1e30f, m1 = -1e30f, l0 = 0.f, l1 = 0.f;

    const uint32_t qOff = sbQ +
        (uint32_t)((wid * 16 + (lane & 15)) * FQL2 + (lane >> 4) * 8) * 2;
    const uint32_t kOff =
        (uint32_t)(((lane >> 4) * 8 + (lane & 7)) * FQL2 + ((lane >> 3) & 1) * 8) * 2;
    const uint32_t vOff =
        (uint32_t)((((lane >> 3) & 1) * 8 + (lane & 7)) * FQL2 + (lane >> 4) * 8) * 2;

    for (int kt = 0; kt < KT; kt++) {
        const int s = kt & 1;
        CP_WAIT(0);
        __syncthreads();
        // Barrier certifies all warps finished reading stage s^1 at kt-1
        // (and makes the Q-tile stores visible on kt==0) -> refill s^1 now.
        if (kt + 1 < KT) fillKV(s ^ 1, kt + 1);

        const uint32_t ksb = sbKV + s * FSTG2;
        const uint32_t vtb = ksb + FKB2;

        // S = (log2e/8) Q K^T  (fp32 accumulators)
        float sacc[8][4];
#pragma unroll
        for (int j = 0; j < 8; j++)
#pragma unroll
            for (int e = 0; e < 4; e++) sacc[j][e] = 0.f;

#pragma unroll
        for (int t = 0; t < 4; t++) {
            uint32_t a[4];
            ldsm4(a, qOff + (uint32_t)(t * 16) * 2);
#pragma unroll
            for (int jp = 0; jp < 4; jp++) {
                uint32_t kq[4];
                ldsm4(kq, ksb + kOff + (uint32_t)(jp * 16 * FQL2 + t * 16) * 2);
                mma_f16(sacc[2 * jp],     a, &kq[0]);
                mma_f16(sacc[2 * jp + 1], a, &kq[2]);
            }
        }

        if (kt * 64 + 63 > qt * 128) {
            const int qr0 = qt * 128 + wid * 16 + lr;
#pragma unroll
            for (int j = 0; j < 8; j++) {
                const int kc = kt * 64 + j * 8 + 2 * lc;
                if (kc     > qr0)     sacc[j][0] = -1e30f;
                if (kc + 1 > qr0)     sacc[j][1] = -1e30f;
                if (kc     > qr0 + 8) sacc[j][2] = -1e30f;
                if (kc + 1 > qr0 + 8) sacc[j][3] = -1e30f;
            }
        }

        float pm0 = -1e30f, pm1 = -1e30f;
#pragma unroll
        for (int j = 0; j < 8; j++) {
            pm0 = fmaxf(pm0, fmaxf(sacc[j][0], sacc[j][1]));
            pm1 = fmaxf(pm1, fmaxf(sacc[j][2], sacc[j][3]));
        }
        pm0 = fmaxf(pm0, __shfl_xor_sync(0xffffffffu, pm0, 1));
        pm0 = fmaxf(pm0, __shfl_xor_sync(0xffffffffu, pm0, 2));
        pm1 = fmaxf(pm1, __shfl_xor_sync(0xffffffffu, pm1, 1));
        pm1 = fmaxf(pm1, __shfl_xor_sync(0xffffffffu, pm1, 2));
        const float nm0 = fmaxf(m0, pm0), nm1 = fmaxf(m1, pm1);

        // Probs via f16x2 ex2 — pp[j][0] = rows lr (c0,c1), pp[j][1] = rows lr+8.
        // These ARE the PV A-fragment registers. Masked lanes: -1e30 packs to
        // -inf, ex2 -> exact 0.
        uint32_t pp[8][2];
        float sum0 = 0.f, sum1 = 0.f;
#pragma unroll
        for (int j = 0; j < 8; j++) {
            pp[j][0] = ex2_f16x2(pack_f16(sacc[j][1] - nm0, sacc[j][0] - nm0));
            pp[j][1] = ex2_f16x2(pack_f16(sacc[j][3] - nm1, sacc[j][2] - nm1));
            const float2 f0 = __half22float2(*(__half2*)&pp[j][0]);
            const float2 f1 = __half22float2(*(__half2*)&pp[j][1]);
            sum0 += f0.x + f0.y;
            sum1 += f1.x + f1.y;
        }
        sum0 += __shfl_xor_sync(0xffffffffu, sum0, 1);
        sum0 += __shfl_xor_sync(0xffffffffu, sum0, 2);
        sum1 += __shfl_xor_sync(0xffffffffu, sum1, 1);
        sum1 += __shfl_xor_sync(0xffffffffu, sum1, 2);

        const float al0 = exp2f(m0 - nm0), al1 = exp2f(m1 - nm1);
        l0 = l0 * al0 + sum0; l1 = l1 * al1 + sum1;
        m0 = nm0; m1 = nm1;
#pragma unroll
        for (int j = 0; j < 8; j++) {
            oacc[j][0] *= al0; oacc[j][1] *= al0;
            oacc[j][2] *= al1; oacc[j][3] *= al1;
        }

        // O += P V  (fp32 accumulators; A-fragments = pp, zero repacking)
#pragma unroll
        for (int t = 0; t < 4; t++) {
            uint32_t ph[4] = { pp[2 * t][0], pp[2 * t][1],
                               pp[2 * t + 1][0], pp[2 * t + 1][1] };
#pragma unroll
            for (int jp = 0; jp < 4; jp++) {
                uint32_t vq[4];
                ldsm4t(vq, vtb + vOff + (uint32_t)(t * 16 * FQL2 + jp * 16) * 2);
                mma_f16(oacc[2 * jp],     ph, &vq[0]);
                mma_f16(oacc[2 * jp + 1], ph, &vq[2]);
            }
        }
    }

    // Epilogue: normalize, emit fp16 (feeds fp16 out-proj)
    const float inv0 = 1.f / l0, inv1 = 1.f / l1;
    const int r0 = qt * 128 + wid * 16 + lr;
#pragma unroll
    for (int j2 = 0; j2 < 8; j2++) {
        const int col = h * 64 + j2 * 8 + 2 * lc;
        *(uint32_t*)&g_ah[((size_t)b * Sn + r0) * Dn + col] =
            pack_f16(oacc[j2][1] * inv0, oacc[j2][0] * inv0);
        *(uint32_t*)&g_ah[((size_t)b * Sn + r0 + 8) * Dn + col] =
            pack_f16(oacc[j2][3] * inv1, oacc[j2][2] * inv1);
    }
}

// ---------------------------------------------------------------------------

extern "C" void kernel_launch(void* const* d_in, const int* in_sizes, int n_in,
                              void* d_out, int out_size)
{
    const float* x     = (const float*)d_in[0];  // [B,S,D]
    const float* w_qkv = (const float*)d_in[1];  // [3,H,DK,D]
    const float* w_o   = (const float*)d_in[2];  // [D,D]
    float* out = (float*)d_out;                  // [B,S,D]

    const int M = Bn * Sn;   // 8192

    (void)cudaFuncSetAttribute(flash_f16,
                               cudaFuncAttributeMaxDynamicSharedMemorySize, F_SMEM);
    (void)cudaFuncSetAttribute(gemm_f16<0>,
                               cudaFuncAttributeMaxDynamicSharedMemorySize, G_SMEM);
    (void)cudaFuncSetAttribute(gemm_f16<1>,
                               cudaFuncAttributeMaxDynamicSharedMemorySize, G_SMEM);

    __half *xh, *wh, *woh, *ah;
    (void)cudaGetSymbolAddress((void**)&xh, g_xh);
    (void)cudaGetSymbolAddress((void**)&wh, g_wh);
    (void)cudaGetSymbolAddress((void**)&woh, g_woh);
    (void)cudaGetSymbolAddress((void**)&ah, g_ah);

    // 0) fp32 -> fp16 pre-pass, single launch
    {
        const int nx  = M * Dn / 4;
        const int nw  = 3 * Hn * DKn * Dn / 4;
        const int nwo = Dn * Dn / 4;
        const int tot = nx + nw + nwo;
        cvt_all<<<(tot + 255) / 256, 256>>>(
            (const float4*)x, (const float4*)w_qkv, (const float4*)w_o,
            (uint2*)xh, (uint2*)wh, (uint2*)woh, nx, nw, nwo);
    }

    // 1) QKV projection (fp16 mma) -> g_qh/g_kh/g_vh
    {
        dim3 grid(3 * Hn * DKn / 128, M / 128);  // (24, 64)
        gemm_f16<0><<<grid, 256, G_SMEM>>>(xh, wh, nullptr, M, 3 * Hn * DKn, Dn);
    }

    // 2) Causal flash attention (fp16 mma) -> g_ah
    {
        dim3 grid(Sn / 128, Hn, Bn);  // (16, 16, 4)
        flash_f16<<<grid, 256, F_SMEM>>>();
    }

    // 3) Output projection (fp16 mma) -> out
    {
        dim3 grid(Dn / 128, M / 128);  // (8, 64)
        gemm_f16<1><<<grid, 256, G_SMEM>>>(ah, woh, out, M, Dn, Dn);
    }
}